// round 13
// baseline (speedup 1.0000x reference)
#include <cuda_runtime.h>
#include <cstdint>

// EdgeEmbAttentionAggregator — round 11: all 8 warps issue MMAs (warp w owns
// m-tile / node w, acc 64->32 regs). SIMT x-GEMM/edge-score work runs serially
// after the GEMM inside the same phase. Epilogue fully warp-local per node.

namespace {

constexpr int S    = 16;
constexpr int IND  = 128;
constexpr int D    = 64;
constexpr int E    = 32;
constexpr int B    = 8;
constexpr int ROWS = B * S;            // 128
constexpr int THREADS = 256;
constexpr int OUTD = 160;
constexpr float LRELU_ALPHA = 0.8f;

// dynamic smem offsets (bytes)
constexpr int OFF_AHI = 0;                  // 128 x 128 bf16 = 32768
constexpr int OFF_ALO = 32768;              // 32768
constexpr int OFF_BHI = 65536;              // 128 x 64 bf16 = 16384
constexpr int OFF_BLO = 81920;              // 16384
constexpr int OFF_ATT = 98304;              // 128 f32
constexpr int OFF_SC  = OFF_ATT + 512;      // 128 f32
constexpr int OFF_SXA = OFF_SC  + 512;      // 8 f32
constexpr int OFF_OUT = OFF_SXA + 32;       // 8*160 f32 = 5120
constexpr int SMEM_BYTES = OFF_OUT + 5120;  // 104480

typedef unsigned long long ull;

__device__ __forceinline__ uint32_t smem_u32(const void* p) {
    uint32_t a;
    asm("{ .reg .u64 t; cvta.to.shared.u64 t, %1; cvt.u32.u64 %0, t; }"
        : "=r"(a) : "l"(p));
    return a;
}
__device__ __forceinline__ ull ffma2(ull a, ull b, ull c) {
    ull d;
    asm("fma.rn.f32x2 %0, %1, %2, %3;" : "=l"(d) : "l"(a), "l"(b), "l"(c));
    return d;
}
__device__ __forceinline__ ull splat2(float x) {
    ull r;
    asm("mov.b64 %0, {%1, %1};" : "=l"(r) : "f"(x));
    return r;
}
__device__ __forceinline__ float2 unpack2(ull v) {
    float lo, hi;
    asm("mov.b64 {%0, %1}, %2;" : "=f"(lo), "=f"(hi) : "l"(v));
    return make_float2(lo, hi);
}
// pack: result lo16 = bf16(b), hi16 = bf16(a)  -> memory order (b, a)
__device__ __forceinline__ uint32_t pack_bf16(float a_hi, float b_lo) {
    uint32_t r;
    asm("cvt.rn.bf16x2.f32 %0, %1, %2;" : "=r"(r) : "f"(a_hi), "f"(b_lo));
    return r;
}
__device__ __forceinline__ float bf_lo(uint32_t p) { return __uint_as_float(p << 16); }
__device__ __forceinline__ float bf_hi(uint32_t p) { return __uint_as_float(p & 0xFFFF0000u); }

__device__ __forceinline__ void ldsm_x4(uint32_t addr, uint32_t* r) {
    asm volatile("ldmatrix.sync.aligned.m8n8.x4.shared.b16 {%0,%1,%2,%3}, [%4];"
        : "=r"(r[0]), "=r"(r[1]), "=r"(r[2]), "=r"(r[3]) : "r"(addr));
}
__device__ __forceinline__ void ldsm_x4t(uint32_t addr, uint32_t* r) {
    asm volatile("ldmatrix.sync.aligned.m8n8.x4.trans.shared.b16 {%0,%1,%2,%3}, [%4];"
        : "=r"(r[0]), "=r"(r[1]), "=r"(r[2]), "=r"(r[3]) : "r"(addr));
}
__device__ __forceinline__ void mma_bf16(float* d, const uint32_t* a,
                                         uint32_t b0, uint32_t b1) {
    asm volatile(
        "mma.sync.aligned.m16n8k16.row.col.f32.bf16.bf16.f32 "
        "{%0,%1,%2,%3}, {%4,%5,%6,%7}, {%8,%9}, {%0,%1,%2,%3};"
        : "+f"(d[0]), "+f"(d[1]), "+f"(d[2]), "+f"(d[3])
        : "r"(a[0]), "r"(a[1]), "r"(a[2]), "r"(a[3]), "r"(b0), "r"(b1));
}

} // namespace

__global__ void __launch_bounds__(THREADS, 2)
gat_mma_kernel(const float* __restrict__ gIn,
               const float* __restrict__ gNb,
               const float* __restrict__ gEe,
               const float* __restrict__ gW,
               const float* __restrict__ gW2,
               const float* __restrict__ gA,
               float* __restrict__ gOut,
               int N)
{
    extern __shared__ char smc[];
    float* sAtt = reinterpret_cast<float*>(smc + OFF_ATT);
    float* sSc  = reinterpret_cast<float*>(smc + OFF_SC);
    float* sSxa = reinterpret_cast<float*>(smc + OFF_SXA);
    float* sOut = reinterpret_cast<float*>(smc + OFF_OUT);
    const uint32_t sb = smem_u32(smc);

    const int tid    = threadIdx.x;
    const int node0  = blockIdx.x * B;
    const int vnodes = min(B, N - node0);
    const int vrows  = vnodes * S;

    // ============ P0: split-stage A and B into bf16 hi/lo (swizzled) ========
    {
        const float4* nb4 = reinterpret_cast<const float4*>(gNb) + (size_t)node0 * S * 32;
        #pragma unroll
        for (int t = 0; t < 8; t++) {
            int idx = tid + t * THREADS;       // 0..2047
            int r = idx >> 4, u = idx & 15;
            float4 fa = make_float4(0.f,0.f,0.f,0.f), fb = fa;
            if (r < vrows) { fa = __ldg(nb4 + r*32 + u*2); fb = __ldg(nb4 + r*32 + u*2 + 1); }
            uint32_t h0 = pack_bf16(fa.y, fa.x), h1 = pack_bf16(fa.w, fa.z);
            uint32_t h2 = pack_bf16(fb.y, fb.x), h3 = pack_bf16(fb.w, fb.z);
            uint32_t l0 = pack_bf16(fa.y - bf_hi(h0), fa.x - bf_lo(h0));
            uint32_t l1 = pack_bf16(fa.w - bf_hi(h1), fa.z - bf_lo(h1));
            uint32_t l2 = pack_bf16(fb.y - bf_hi(h2), fb.x - bf_lo(h2));
            uint32_t l3 = pack_bf16(fb.w - bf_hi(h3), fb.z - bf_lo(h3));
            uint32_t off = r * 256 + ((u ^ (r & 7)) << 4);
            *reinterpret_cast<uint4*>(smc + OFF_AHI + off) = make_uint4(h0,h1,h2,h3);
            *reinterpret_cast<uint4*>(smc + OFF_ALO + off) = make_uint4(l0,l1,l2,l3);
        }
        const float4* w24 = reinterpret_cast<const float4*>(gW2);
        #pragma unroll
        for (int t = 0; t < 4; t++) {
            int idx = tid + t * THREADS;       // 0..1023
            int k = idx >> 3, u = idx & 7;
            float4 fa = __ldg(w24 + k*16 + u*2);
            float4 fb = __ldg(w24 + k*16 + u*2 + 1);
            uint32_t h0 = pack_bf16(fa.y, fa.x), h1 = pack_bf16(fa.w, fa.z);
            uint32_t h2 = pack_bf16(fb.y, fb.x), h3 = pack_bf16(fb.w, fb.z);
            uint32_t l0 = pack_bf16(fa.y - bf_hi(h0), fa.x - bf_lo(h0));
            uint32_t l1 = pack_bf16(fa.w - bf_hi(h1), fa.z - bf_lo(h1));
            uint32_t l2 = pack_bf16(fb.y - bf_hi(h2), fb.x - bf_lo(h2));
            uint32_t l3 = pack_bf16(fb.w - bf_hi(h3), fb.z - bf_lo(h3));
            uint32_t off = k * 128 + ((u ^ (k & 7)) << 4);
            *reinterpret_cast<uint4*>(smc + OFF_BHI + off) = make_uint4(h0,h1,h2,h3);
            *reinterpret_cast<uint4*>(smc + OFF_BLO + off) = make_uint4(l0,l1,l2,l3);
        }
    }
    __syncthreads();

    // ============ P1: GEMM — ALL 8 warps, warp w = m-tile / node w ==========
    float acc[8][4];
    const int w    = tid >> 5;
    const int lane = tid & 31;
    const int g    = lane >> 2;
    const int tig  = lane & 3;
    const int tsel = lane >> 3;
    const int lr   = lane & 7;
    const int rowoff = ((tsel & 1) << 3) + lr;   // ldmatrix row within 16
    const int uoff   = tsel >> 1;                // ldmatrix 16B-unit offset

    #pragma unroll
    for (int nt = 0; nt < 8; nt++)
        #pragma unroll
        for (int j = 0; j < 4; j++) acc[nt][j] = 0.f;

    #pragma unroll 2
    for (int ks = 0; ks < 8; ks++) {
        uint32_t ahi[4], alo[4];
        {
            int row  = w * 16 + rowoff;
            int unit = 2*ks + uoff;
            uint32_t off = row * 256 + ((unit ^ (row & 7)) << 4);
            ldsm_x4(sb + OFF_AHI + off, ahi);
            ldsm_x4(sb + OFF_ALO + off, alo);
        }
        #pragma unroll
        for (int hp = 0; hp < 2; hp++) {
            uint32_t bh[2][4], bl[2][4];
            #pragma unroll
            for (int p = 0; p < 2; p++) {
                int np   = 2*hp + p;
                int krow = ks * 16 + rowoff;
                int unit = 2*np + uoff;
                uint32_t off = krow * 128 + ((unit ^ (krow & 7)) << 4);
                ldsm_x4t(sb + OFF_BHI + off, bh[p]);
                ldsm_x4t(sb + OFF_BLO + off, bl[p]);
            }
            // term-major: dependent writes to one acc are 4 MMAs apart
            #pragma unroll
            for (int p = 0; p < 2; p++) {
                mma_bf16(acc[4*hp + 2*p],     ahi, bh[p][0], bh[p][1]);
                mma_bf16(acc[4*hp + 2*p + 1], ahi, bh[p][2], bh[p][3]);
            }
            #pragma unroll
            for (int p = 0; p < 2; p++) {
                mma_bf16(acc[4*hp + 2*p],     alo, bh[p][0], bh[p][1]);
                mma_bf16(acc[4*hp + 2*p + 1], alo, bh[p][2], bh[p][3]);
            }
            #pragma unroll
            for (int p = 0; p < 2; p++) {
                mma_bf16(acc[4*hp + 2*p],     ahi, bl[p][0], bl[p][1]);
                mma_bf16(acc[4*hp + 2*p + 1], ahi, bl[p][2], bl[p][3]);
            }
        }
    }

    // ============ P1b: serial SIMT work (x-GEMM / edge scores) ==============
    if (tid < 128) {
        // x = input @ W : 16 lanes per node, 4 cols each; fused s_x
        const int n    = tid >> 4;
        const int cg16 = tid & 15;
        const int nr   = min(node0 + n, N - 1);
        const float4* in4 = reinterpret_cast<const float4*>(gIn + (size_t)nr * IND);
        const float* wp   = gW + 4 * cg16;

        ull x0 = 0ull, x1 = 0ull;
        #pragma unroll 8
        for (int kq = 0; kq < 32; kq++) {
            float4 av4 = __ldg(in4 + kq);
            #pragma unroll
            for (int j = 0; j < 4; j++) {
                const int k = 4 * kq + j;
                ulonglong2 bp = __ldg(reinterpret_cast<const ulonglong2*>(wp + k * D));
                float a = (j == 0) ? av4.x : (j == 1) ? av4.y
                        : (j == 2) ? av4.z : av4.w;
                ull av = splat2(a);
                x0 = ffma2(av, bp.x, x0);
                x1 = ffma2(av, bp.y, x1);
            }
        }
        float2 v0 = unpack2(x0), v1 = unpack2(x1);
        *reinterpret_cast<float4*>(sOut + n * OUTD + 4 * cg16) =
            make_float4(v0.x, v0.y, v1.x, v1.y);

        float4 ax = __ldg(reinterpret_cast<const float4*>(gA + 4 * cg16));
        float part = v0.x * ax.x + v0.y * ax.y + v1.x * ax.z + v1.y * ax.w;
        #pragma unroll
        for (int off = 8; off > 0; off >>= 1)
            part += __shfl_xor_sync(0xffffffffu, part, off, 16);
        if (cg16 == 0) sSxa[n] = part;
    } else {
        // edge scores: 8 threads per row
        const int t = tid - 128;
        const float4* ee4 = reinterpret_cast<const float4*>(gEe)
                            + (size_t)node0 * S * (E / 4);
        #pragma unroll
        for (int it = 0; it < 8; it++) {
            int i   = t + it * 128;
            int row = i >> 3;
            int ch  = i & 7;
            float4 v = (row < vrows) ? __ldg(ee4 + i)
                                     : make_float4(0.f, 0.f, 0.f, 0.f);
            float4 ae = __ldg(reinterpret_cast<const float4*>(gA + 2 * D + 4 * ch));
            float p = v.x * ae.x + v.y * ae.y + v.z * ae.z + v.w * ae.w;
            p += __shfl_xor_sync(0xffffffffu, p, 4, 8);
            p += __shfl_xor_sync(0xffffffffu, p, 2, 8);
            p += __shfl_xor_sync(0xffffffffu, p, 1, 8);
            if (ch == 0) sSc[row] = p;
        }
    }
    __syncthreads();

    // ============ P2: warp-local scores/softmax/h'/h_edge for node w ========
    {
        float wN[8][2];
        #pragma unroll
        for (int nt = 0; nt < 8; nt++) {
            wN[nt][0] = __ldg(gA + D + 8*nt + 2*tig);
            wN[nt][1] = __ldg(gA + D + 8*nt + 2*tig + 1);
        }
        const int nd = w;
        const int R  = nd * 16;
        float pa = 0.f, pb = 0.f;
        #pragma unroll
        for (int nt = 0; nt < 8; nt++) {
            pa += acc[nt][0]*wN[nt][0] + acc[nt][1]*wN[nt][1];
            pb += acc[nt][2]*wN[nt][0] + acc[nt][3]*wN[nt][1];
        }
        pa += __shfl_xor_sync(0xffffffffu, pa, 1);
        pa += __shfl_xor_sync(0xffffffffu, pa, 2);
        pb += __shfl_xor_sync(0xffffffffu, pb, 1);
        pb += __shfl_xor_sync(0xffffffffu, pb, 2);

        float sa  = pa + sSc[R + g]     + sSxa[nd];
        float sbv = pb + sSc[R + g + 8] + sSxa[nd];
        sa  = (sa  > 0.f) ? sa  : LRELU_ALPHA * sa;
        sbv = (sbv > 0.f) ? sbv : LRELU_ALPHA * sbv;

        float mx = fmaxf(sa, sbv);
        #pragma unroll
        for (int off = 4; off <= 16; off <<= 1)
            mx = fmaxf(mx, __shfl_xor_sync(0xffffffffu, mx, off));
        float ea = expf(sa - mx), eb = expf(sbv - mx);
        float den = ea + eb;
        #pragma unroll
        for (int off = 4; off <= 16; off <<= 1)
            den += __shfl_xor_sync(0xffffffffu, den, off);
        float inv = 1.f / den;
        float ata = ea * inv, atb = eb * inv;
        if (tig == 0) { sAtt[R + g] = ata; sAtt[R + g + 8] = atb; }

        // h' = att-weighted rows, butterfly-reduced over g
        float h[8][2];
        #pragma unroll
        for (int nt = 0; nt < 8; nt++) {
            h[nt][0] = ata * acc[nt][0] + atb * acc[nt][2];
            h[nt][1] = ata * acc[nt][1] + atb * acc[nt][3];
        }
        #pragma unroll
        for (int off = 4; off <= 16; off <<= 1)
            #pragma unroll
            for (int nt = 0; nt < 8; nt++) {
                h[nt][0] += __shfl_xor_sync(0xffffffffu, h[nt][0], off);
                h[nt][1] += __shfl_xor_sync(0xffffffffu, h[nt][1], off);
            }
        if (g == 0) {
            #pragma unroll
            for (int nt = 0; nt < 8; nt++)
                *reinterpret_cast<float2*>(sOut + nd*OUTD + D + 8*nt + 2*tig) =
                    make_float2(h[nt][0], h[nt][1]);
        }

        // h_edge for node w (warp-local: uses only this warp's sAtt values)
        {
            const float* eb2 = gEe + ((size_t)min(node0 + nd, N - 1) * S) * E + lane;
            float att0 = __shfl_sync(0xffffffffu, tig == 0 ? ata : 0.f, 4 * 0);
            // gather all 16 attention values via shuffles from lanes tig==0
            float hsum = 0.f;
            #pragma unroll
            for (int s = 0; s < 8; s++) {
                float a0 = __shfl_sync(0xffffffffu, ata, 4 * s);
                float a1 = __shfl_sync(0xffffffffu, atb, 4 * s);
                hsum += a0 * __ldg(eb2 + s * E);
                hsum += a1 * __ldg(eb2 + (s + 8) * E);
            }
            (void)att0;
            sOut[nd * OUTD + 2 * D + lane] = hsum;
        }
    }
    __syncthreads();

    // ============ P4: coalesced output ======================================
    {
        float4* o4 = reinterpret_cast<float4*>(gOut) + (size_t)node0 * (OUTD / 4);
        const float4* s4 = reinterpret_cast<const float4*>(sOut);
        const int lim = vnodes * (OUTD / 4);
        for (int i = tid; i < lim; i += THREADS) o4[i] = s4[i];
    }
}

extern "C" void kernel_launch(void* const* d_in, const int* in_sizes, int n_in,
                              void* d_out, int out_size)
{
    const float* gIn = (const float*)d_in[0];   // input      (N, 128)
    const float* gNb = (const float*)d_in[1];   // neigh_feat (N*16, 128)
    const float* gEe = (const float*)d_in[2];   // edge_emb   (N*16, 32)
    const float* gW  = (const float*)d_in[3];   // W  (128, 64)
    const float* gW2 = (const float*)d_in[4];   // W2 (128, 64)
    const float* gA  = (const float*)d_in[5];   // a  (160, 1)
    float* gOut = (float*)d_out;                // (N, 160)

    const int N = in_sizes[0] / IND;

    cudaFuncSetAttribute(gat_mma_kernel,
                         cudaFuncAttributeMaxDynamicSharedMemorySize, SMEM_BYTES);
    const int grid = (N + B - 1) / B;
    gat_mma_kernel<<<grid, THREADS, SMEM_BYTES>>>(gIn, gNb, gEe, gW, gW2, gA, gOut, N);
}